// round 1
// baseline (speedup 1.0000x reference)
#include <cuda_runtime.h>
#include <cstdint>

typedef unsigned long long u64;

#define BATCH 32
#define HID   64
#define CHUNK 4096
#define CMASK (CHUNK-1)
#define LOGC  12

__device__ __forceinline__ u64 fma2(u64 a, u64 b, u64 c){
    u64 d; asm("fma.rn.f32x2 %0, %1, %2, %3;" : "=l"(d) : "l"(a), "l"(b), "l"(c)); return d;
}
__device__ __forceinline__ u64 add2(u64 a, u64 b){
    u64 d; asm("add.rn.f32x2 %0, %1, %2;" : "=l"(d) : "l"(a), "l"(b)); return d;
}
__device__ __forceinline__ float hsum2(u64 a){
    float lo, hi; asm("mov.b64 {%0,%1}, %2;" : "=f"(lo), "=f"(hi) : "l"(a)); return lo + hi;
}
// sigmoid via MUFU ex2+rcp chain: rel err ~1e-7
__device__ __forceinline__ float fsig(float v){
    float e = __expf(-v);
    return __fdividef(1.0f, 1.0f + e);
}
// tanh(v) = 1 - 2/(exp(2v)+1); saturates correctly at +/-inf
__device__ __forceinline__ float ftanh(float v){
    float e = __expf(2.0f * v);
    return 1.0f - __fdividef(2.0f, e + 1.0f);
}

// One CTA per batch row. 128 threads: pair (2i, 2i+1) owns hidden unit i.
// Lane p=0: full 64-dot for r-gate; lane p=1: full 64-dot for z-gate.
// Both lanes: half 32-dot for n-gate (combined via shfl_xor 1).
__global__ void __launch_bounds__(128, 1)
gru_kernel(const float* __restrict__ x, const float* __restrict__ w_ih,
           const float* __restrict__ w_hh, const float* __restrict__ b_ih,
           const float* __restrict__ b_hh, float* __restrict__ states, int T)
{
    __shared__ __align__(16) float hbuf[2][HID];
    __shared__ __align__(16) float xs[2][CHUNK];

    const int tid = threadIdx.x;
    const int b   = blockIdx.x;
    const int i   = tid >> 1;
    const int p   = tid & 1;
    const int ia  = i + 64 * p;   // gate-a row: r (p=0) or z (p=1)
    const int in_ = 128 + i;      // n-gate row

    // --- load weights into registers (packed f32x2) ---
    u64 wa[32];
    {
        const u64* was = (const u64*)(w_hh + ia * 64);
        #pragma unroll
        for (int q = 0; q < 32; q++) wa[q] = was[q];
    }
    u64 wn[16];
    {
        const u64* wns = (const u64*)(w_hh + in_ * 64 + 32 * p);
        #pragma unroll
        for (int q = 0; q < 16; q++) wn[q] = wns[q];
    }

    const float bhh_a = b_hh[ia], bih_a = b_ih[ia], wih_a = w_ih[ia];
    const float bhh_n = b_hh[in_], bih_n = b_ih[in_], wih_n = w_ih[in_];
    const float ca = bhh_a + bih_a;

    const float* xrow = x + (size_t)b * T;

    // init: h0 = 0, preload x chunk 0
    if (tid < HID) hbuf[0][tid] = 0.0f;
    {
        const float4* src = (const float4*)xrow;
        float4* dst = (float4*)xs[0];
        #pragma unroll
        for (int q = 0; q < CHUNK / 4 / 128; q++) dst[tid + q * 128] = src[tid + q * 128];
    }
    __syncthreads();

    float* sout = states + ((size_t)b * T) * HID + i;

    for (int t = 0; t < T; ++t) {
        // prefetch next x chunk into the idle buffer (block-uniform branch)
        if ((t & CMASK) == 0) {
            int nc = (t >> LOGC) + 1;
            if (nc * CHUNK < T) {
                const float4* src = (const float4*)(xrow + (size_t)nc * CHUNK);
                float4* dst = (float4*)xs[nc & 1];
                #pragma unroll
                for (int q = 0; q < CHUNK / 4 / 128; q++) dst[tid + q * 128] = src[tid + q * 128];
            }
        }

        const int cur = t & 1;
        const float* hc = hbuf[cur];
        const float xt = xs[(t >> LOGC) & 1][t & CMASK];
        const float hprev = hc[i];

        // full 64-dot for gate a (r or z)
        u64 a0 = 0, a1 = 0, a2 = 0, a3 = 0;
        const ulonglong2* hs = (const ulonglong2*)hc;
        #pragma unroll
        for (int q = 0; q < 16; q += 2) {
            ulonglong2 h0 = hs[q];
            ulonglong2 h1 = hs[q + 1];
            a0 = fma2(h0.x, wa[2 * q],     a0);
            a1 = fma2(h0.y, wa[2 * q + 1], a1);
            a2 = fma2(h1.x, wa[2 * q + 2], a2);
            a3 = fma2(h1.y, wa[2 * q + 3], a3);
        }
        float sa = hsum2(add2(add2(a0, a1), add2(a2, a3)));
        float ga = fsig(sa + fmaf(xt, wih_a, ca));   // starts before n-dot finishes

        // half 32-dot for n-gate
        u64 n0 = 0, n1 = 0;
        const ulonglong2* hsn = (const ulonglong2*)(hc + 32 * p);
        #pragma unroll
        for (int q = 0; q < 8; q++) {
            ulonglong2 hq = hsn[q];
            n0 = fma2(hq.x, wn[2 * q],     n0);
            n1 = fma2(hq.y, wn[2 * q + 1], n1);
        }
        float snp = hsum2(add2(n0, n1));
        float sn  = snp + __shfl_xor_sync(0xffffffffu, snp, 1);
        float gb  = __shfl_xor_sync(0xffffffffu, ga, 1);
        float r = p ? gb : ga;
        float z = p ? ga : gb;
        float hn = sn + bhh_n;
        float xn = fmaf(xt, wih_n, bih_n);
        float n  = ftanh(fmaf(r, hn, xn));
        float hnew = fmaf(z, hprev - n, n);   // (1-z)*n + z*h

        if (!p) {
            hbuf[cur ^ 1][i] = hnew;
            sout[(size_t)t * HID] = hnew;
        }
        __syncthreads();
    }
}

// out[n] = dot(states[n,:], w_lin) + b_lin + x[n]
__global__ void head_kernel(const float* __restrict__ st, const float* __restrict__ x,
                            const float* __restrict__ wl, const float* __restrict__ bl,
                            float* __restrict__ out, int BT)
{
    int n = blockIdx.x * blockDim.x + threadIdx.x;
    if (n >= BT) return;
    const float4* s4 = (const float4*)(st + (size_t)n * HID);
    const float4* w4 = (const float4*)wl;
    float acc = 0.0f;
    #pragma unroll
    for (int j = 0; j < 16; j++) {
        float4 v = s4[j], w = w4[j];
        acc += v.x * w.x;
        acc += v.y * w.y;
        acc += v.z * w.z;
        acc += v.w * w.w;
    }
    out[n] = acc + bl[0] + x[n];
}

extern "C" void kernel_launch(void* const* d_in, const int* in_sizes, int n_in,
                              void* d_out, int out_size)
{
    const float* x     = (const float*)d_in[0];
    const float* w_ih  = (const float*)d_in[1];
    const float* w_hh  = (const float*)d_in[2];
    const float* b_ih  = (const float*)d_in[3];
    const float* b_hh  = (const float*)d_in[4];
    const float* w_lin = (const float*)d_in[5];
    const float* b_lin = (const float*)d_in[6];

    float* out = (float*)d_out;
    const int BT = in_sizes[0];          // B * T
    const int T  = BT / BATCH;
    float* states = out + BT;            // d_out = [out | states]

    gru_kernel<<<BATCH, 128>>>(x, w_ih, w_hh, b_ih, b_hh, states, T);
    head_kernel<<<(BT + 255) / 256, 256>>>(states, x, w_lin, b_lin, out, BT);
}